// round 16
// baseline (speedup 1.0000x reference)
#include <cuda_runtime.h>
#include <cstdint>

// out[e, 0:128]   = node_states[src[e], :]
// out[e, 128:256] = node_states[tgt[e], :]
// R15 confirmed-best config (49.25/49.34us on two runs): 2 edges/warp,
// block 256, int2 index loads (default policy), L2::evict_last gathers,
// evict-first (__stcs) stores.
// This round: + L1::no_allocate on the gathers. Gather reuse per SM is ~0
// (5.12 MB set, 64 touches/row spread over 148 SMs), so L1 allocation of
// gather lines is pure churn in the unit ncu ranks #1 (L1tex 74-76%).
// L2 pin (evict_last) is unchanged — data flows L2 -> registers directly.
// Binder: 328 MB HBM write stream at ~6.65 TB/s effective (~83% of spec).

__device__ __forceinline__ float4 ldg_l2last_l1skip(const float4* p, uint64_t pol) {
    float4 v;
    asm volatile(
        "ld.global.nc.L1::no_allocate.L2::cache_hint.v4.b32 {%0,%1,%2,%3}, [%4], %5;"
        : "=f"(v.x), "=f"(v.y), "=f"(v.z), "=f"(v.w)
        : "l"(p), "l"(pol));
    return v;
}

__global__ __launch_bounds__(256) void node_propagate_kernel(
    const float4* __restrict__ ns,   // [N_NODES, 32] as float4
    const int* __restrict__ src,     // [E] int32
    const int* __restrict__ tgt,     // [E] int32
    float4* __restrict__ out,        // [E, 64] as float4
    int nPairs)                      // E/2
{
    const int gwarp = (int)((blockIdx.x * (unsigned)blockDim.x + threadIdx.x) >> 5);
    const int lane  = threadIdx.x & 31;
    if (gwarp >= nPairs) return;
    const int e0 = gwarp * 2;

    // evict_last policy for the reused gather set (L2 retention pin).
    uint64_t pol;
    asm("createpolicy.fractional.L2::evict_last.b64 %0, 1.0;" : "=l"(pol));

    // Index pairs: adjacent int32s -> one 8B broadcast load each
    // (default policy — lines shared across warps; .cs regressed in R14).
    const int2 s2 = *(const int2*)(src + e0);
    const int2 t2 = *(const int2*)(tgt + e0);

    // 4 independent gathers in flight; L2-pinned, L1 bypassed.
    const float4 a0 = ldg_l2last_l1skip(&ns[(size_t)s2.x * 32 + lane], pol);
    const float4 b0 = ldg_l2last_l1skip(&ns[(size_t)t2.x * 32 + lane], pol);
    const float4 a1 = ldg_l2last_l1skip(&ns[(size_t)s2.y * 32 + lane], pol);
    const float4 b1 = ldg_l2last_l1skip(&ns[(size_t)t2.y * 32 + lane], pol);

    // Evict-first stores: prompt full-line drain, protect the gather set.
    float4* o = out + (size_t)e0 * 64;
    __stcs(o +      lane, a0);
    __stcs(o + 32 + lane, b0);
    __stcs(o + 64 + lane, a1);
    __stcs(o + 96 + lane, b1);
}

// Tail for odd E (unused for E=320000).
__global__ void node_propagate_tail(
    const float4* __restrict__ ns,
    const int* __restrict__ src,
    const int* __restrict__ tgt,
    float4* __restrict__ out,
    int e)
{
    const int lane = threadIdx.x & 31;
    const int s = __ldg(&src[e]);
    const int t = __ldg(&tgt[e]);
    const float4 a = __ldg(&ns[(size_t)s * 32 + lane]);
    const float4 b = __ldg(&ns[(size_t)t * 32 + lane]);
    float4* o = out + (size_t)e * 64;
    __stcs(o + lane,      a);
    __stcs(o + 32 + lane, b);
}

extern "C" void kernel_launch(void* const* d_in, const int* in_sizes, int n_in,
                              void* d_out, int out_size)
{
    const float4* ns  = (const float4*)d_in[0];
    const int*    src = (const int*)d_in[1];
    const int*    tgt = (const int*)d_in[2];
    float4*       out = (float4*)d_out;

    const int E      = in_sizes[1];   // 320000 edges
    const int nPairs = E / 2;

    const int threads = 256;          // 8 warps -> 16 edges per block
    const int blocks  = (nPairs * 32 + threads - 1) / threads;

    node_propagate_kernel<<<blocks, threads>>>(ns, src, tgt, out, nPairs);

    if (E & 1)
        node_propagate_tail<<<1, 32>>>(ns, src, tgt, out, E - 1);
}